// round 1
// baseline (speedup 1.0000x reference)
#include <cuda_runtime.h>

#define BATCH 8
#define SEQ   2048
#define HID   1024
#define WHALF 64
#define NEG_INF -1e9f

// Scratch for QW = repr @ W  (64 MB) — __device__ global, no allocation.
__device__ float g_qw[(size_t)BATCH * SEQ * HID];

// ---------------------------------------------------------------------------
// Kernel 1: SGEMM  C[M,N] = A[M,K] * B[K,N],  M=16384, N=K=1024 (fp32)
// 64x64 block tile, BK=16, 256 threads, 4x4 micro-tile.
// ---------------------------------------------------------------------------
__global__ __launch_bounds__(256) void gemm_qw_kernel(
    const float* __restrict__ A, const float* __restrict__ B)
{
    constexpr int K = HID, N = HID;
    constexpr int BM = 64, BN = 64, BK = 16;

    __shared__ float As[BK][BM];      // transposed: As[k][m]
    __shared__ float Bs[BK][BN];

    const int tid = threadIdx.x;
    const int tx = tid % 16;          // 0..15 -> 4 cols each
    const int ty = tid / 16;          // 0..15 -> 4 rows each
    const int row0 = blockIdx.y * BM;
    const int col0 = blockIdx.x * BN;

    float acc[4][4] = {};

    const int ar = tid / 4;           // 0..63
    const int ac = (tid % 4) * 4;     // 0,4,8,12
    const int br = tid / 16;          // 0..15
    const int bc = (tid % 16) * 4;    // 0..60

    for (int k0 = 0; k0 < K; k0 += BK) {
        // Load A tile (64x16), store transposed
        float4 a4 = *(const float4*)&A[(size_t)(row0 + ar) * K + k0 + ac];
        As[ac + 0][ar] = a4.x;
        As[ac + 1][ar] = a4.y;
        As[ac + 2][ar] = a4.z;
        As[ac + 3][ar] = a4.w;
        // Load B tile (16x64)
        *(float4*)&Bs[br][bc] = *(const float4*)&B[(size_t)(k0 + br) * N + col0 + bc];
        __syncthreads();

#pragma unroll
        for (int k = 0; k < BK; k++) {
            float4 av = *(const float4*)&As[k][ty * 4];
            float4 bv = *(const float4*)&Bs[k][tx * 4];
            float a[4] = {av.x, av.y, av.z, av.w};
            float b[4] = {bv.x, bv.y, bv.z, bv.w};
#pragma unroll
            for (int i = 0; i < 4; i++)
#pragma unroll
                for (int j = 0; j < 4; j++)
                    acc[i][j] += a[i] * b[j];
        }
        __syncthreads();
    }

#pragma unroll
    for (int i = 0; i < 4; i++) {
        float4 o = {acc[i][0], acc[i][1], acc[i][2], acc[i][3]};
        *(float4*)&g_qw[(size_t)(row0 + ty * 4 + i) * N + col0 + tx * 4] = o;
    }
}

// ---------------------------------------------------------------------------
// Kernel 2: fused windowed attention
// One block per (batch, 64-query tile). Key band = 192 keys (64 + 2*64).
// Phase 1: S[64,192] = QW_tile @ K_band^T  (K=1024), masked
// Phase 2: row softmax in smem
// Phase 3: RA[64,1024] = P @ V_band,  out = repr + relu(RA)
// ---------------------------------------------------------------------------
#define TQ 64
#define TK 192
#define KC 16
#define SP 193          // Sbuf pitch (avoid bank conflicts)
#define VP 68           // Vs pitch

// smem floats: Sbuf 64*193 = 12352, Qs 16*64 = 1024, Ks 16*192 = 3072
// total = 16448 floats = 65792 bytes
#define SMEM_FLOATS (TQ * SP + KC * TQ + KC * TK)

__global__ __launch_bounds__(256) void attn_win_kernel(
    const float* __restrict__ repr, float* __restrict__ out)
{
    extern __shared__ float smem[];
    float* Sbuf = smem;                 // [64][193]
    float* Qs   = smem + TQ * SP;       // [16][64]  (d-major)
    float* Ks   = Qs + KC * TQ;         // [16][192] (d-major)
    float* Vs   = Qs;                   // phase-3 reuse: [16][68]

    const int b  = blockIdx.y;
    const int q0 = blockIdx.x * TQ;
    const int k0 = q0 - WHALF;

    const float* reprB = repr + (size_t)b * SEQ * HID;
    const float* qwB   = g_qw + (size_t)b * SEQ * HID;
    float*       outB  = out  + (size_t)b * SEQ * HID;

    const int tid = threadIdx.x;
    const int tx = tid % 16;
    const int ty = tid / 16;

    // ---- Phase 1: scores -------------------------------------------------
    float acc[4][12];
#pragma unroll
    for (int i = 0; i < 4; i++)
#pragma unroll
        for (int j = 0; j < 12; j++) acc[i][j] = 0.f;

    const int qr = tid / 4;             // 0..63
    const int qc = (tid % 4) * 4;       // 0..12

    for (int d0 = 0; d0 < HID; d0 += KC) {
        // Load Qs (64 x 16, transposed)
        {
            float4 v = *(const float4*)&qwB[(size_t)(q0 + qr) * HID + d0 + qc];
            Qs[(qc + 0) * TQ + qr] = v.x;
            Qs[(qc + 1) * TQ + qr] = v.y;
            Qs[(qc + 2) * TQ + qr] = v.z;
            Qs[(qc + 3) * TQ + qr] = v.w;
        }
        // Load Ks (192 x 16, transposed), zero-fill out-of-range keys
#pragma unroll
        for (int rep = 0; rep < 3; rep++) {
            int kk = qr + rep * 64;
            int j = k0 + kk;
            float4 v = make_float4(0.f, 0.f, 0.f, 0.f);
            if (j >= 0 && j < SEQ)
                v = *(const float4*)&reprB[(size_t)j * HID + d0 + qc];
            Ks[(qc + 0) * TK + kk] = v.x;
            Ks[(qc + 1) * TK + kk] = v.y;
            Ks[(qc + 2) * TK + kk] = v.z;
            Ks[(qc + 3) * TK + kk] = v.w;
        }
        __syncthreads();

#pragma unroll
        for (int k = 0; k < KC; k++) {
            float4 av = *(const float4*)&Qs[k * TQ + ty * 4];
            float a[4] = {av.x, av.y, av.z, av.w};
#pragma unroll
            for (int jj = 0; jj < 12; jj++) {
                float bv = Ks[k * TK + tx + 16 * jj];
                acc[0][jj] += a[0] * bv;
                acc[1][jj] += a[1] * bv;
                acc[2][jj] += a[2] * bv;
                acc[3][jj] += a[3] * bv;
            }
        }
        __syncthreads();
    }

    // Mask + stash to smem. valid iff 0 <= col-row <= 128 and key index in range.
#pragma unroll
    for (int i = 0; i < 4; i++) {
        int row = ty * 4 + i;
#pragma unroll
        for (int jj = 0; jj < 12; jj++) {
            int col = tx + 16 * jj;
            int j = k0 + col;
            int dr = col - row;
            bool valid = (j >= 0) && (j < SEQ) && (dr >= 0) && (dr <= 2 * WHALF);
            Sbuf[row * SP + col] = valid ? acc[i][jj] : NEG_INF;
        }
    }
    __syncthreads();

    // ---- Phase 2: softmax (one thread per row) ---------------------------
    if (tid < TQ) {
        float* rowp = &Sbuf[tid * SP];
        float m = NEG_INF;
#pragma unroll 4
        for (int c = 0; c < TK; c++) m = fmaxf(m, rowp[c]);
        float s = 0.f;
#pragma unroll 4
        for (int c = 0; c < TK; c++) {
            float e = __expf(rowp[c] - m);
            rowp[c] = e;
            s += e;
        }
        float inv = 1.f / s;
#pragma unroll 4
        for (int c = 0; c < TK; c++) rowp[c] *= inv;
    }
    __syncthreads();

    // ---- Phase 3: RA = P @ V, residual + relu ----------------------------
    for (int dc = 0; dc < HID; dc += 64) {
        float o[4][4] = {};
        for (int kt = 0; kt < TK; kt += KC) {
            __syncthreads();   // protect Vs reuse
            {
                int r = tid / 16;            // 0..15
                int c = (tid % 16) * 4;      // 0..60
                int j = k0 + kt + r;
                float4 v = make_float4(0.f, 0.f, 0.f, 0.f);
                if (j >= 0 && j < SEQ)
                    v = *(const float4*)&reprB[(size_t)j * HID + dc + c];
                *(float4*)&Vs[r * VP + c] = v;
            }
            __syncthreads();

#pragma unroll
            for (int k = 0; k < KC; k++) {
                float p0 = Sbuf[(ty * 4 + 0) * SP + kt + k];
                float p1 = Sbuf[(ty * 4 + 1) * SP + kt + k];
                float p2 = Sbuf[(ty * 4 + 2) * SP + kt + k];
                float p3 = Sbuf[(ty * 4 + 3) * SP + kt + k];
                float4 v4 = *(const float4*)&Vs[k * VP + tx * 4];
                float v[4] = {v4.x, v4.y, v4.z, v4.w};
#pragma unroll
                for (int j = 0; j < 4; j++) {
                    o[0][j] += p0 * v[j];
                    o[1][j] += p1 * v[j];
                    o[2][j] += p2 * v[j];
                    o[3][j] += p3 * v[j];
                }
            }
        }
        // epilogue: out = repr + relu(ra)
#pragma unroll
        for (int i = 0; i < 4; i++) {
            int q = q0 + ty * 4 + i;
            float4 r4 = *(const float4*)&reprB[(size_t)q * HID + dc + tx * 4];
            float4 ov;
            ov.x = r4.x + fmaxf(o[i][0], 0.f);
            ov.y = r4.y + fmaxf(o[i][1], 0.f);
            ov.z = r4.z + fmaxf(o[i][2], 0.f);
            ov.w = r4.w + fmaxf(o[i][3], 0.f);
            *(float4*)&outB[(size_t)q * HID + dc + tx * 4] = ov;
        }
    }
}

// ---------------------------------------------------------------------------
extern "C" void kernel_launch(void* const* d_in, const int* in_sizes, int n_in,
                              void* d_out, int out_size)
{
    (void)in_sizes; (void)n_in; (void)out_size;
    const float* repr = (const float*)d_in[0];
    const float* W    = (const float*)d_in[1];
    float* out        = (float*)d_out;

    // QW = repr @ W
    dim3 gb(HID / 64, (BATCH * SEQ) / 64);
    gemm_qw_kernel<<<gb, 256>>>(repr, W);

    // Fused windowed attention (needs > 48KB dynamic smem)
    cudaFuncSetAttribute(attn_win_kernel,
                         cudaFuncAttributeMaxDynamicSharedMemorySize,
                         SMEM_FLOATS * (int)sizeof(float));
    dim3 ga(SEQ / TQ, BATCH);
    attn_win_kernel<<<ga, 256, SMEM_FLOATS * sizeof(float)>>>(repr, out);
}

// round 3
// speedup vs baseline: 1.6360x; 1.6360x over previous
#include <cuda_runtime.h>
#include <cuda_bf16.h>
#include <cstdint>

#define BATCH 8
#define SEQ   2048
#define HID   1024
#define M_TOT (BATCH * SEQ)        // 16384
#define WHALF 64
#define NEG_INF -1e9f

// Scratch (__device__ globals; no allocation allowed)
__device__ float g_qw[(size_t)M_TOT * HID];                       // 64 MB
__device__ __align__(16) __nv_bfloat16 g_a_hi[(size_t)M_TOT * HID];   // 32 MB
__device__ __align__(16) __nv_bfloat16 g_a_lo[(size_t)M_TOT * HID];   // 32 MB
__device__ __align__(16) __nv_bfloat16 g_wt_hi[(size_t)HID * HID];    // 2 MB  [n][k]
__device__ __align__(16) __nv_bfloat16 g_wt_lo[(size_t)HID * HID];    // 2 MB  [n][k]

// ---------------------------------------------------------------------------
// PTX helpers (all architecture-neutral: sm_80-level features only)
// ---------------------------------------------------------------------------
__device__ __forceinline__ uint32_t smem_u32(const void* p) {
    uint32_t a;
    asm("{ .reg .u64 t; cvta.to.shared.u64 t, %1; cvt.u32.u64 %0, t; }" : "=r"(a) : "l"(p));
    return a;
}

#define CP_ASYNC16(dst_u32, src_ptr) \
    asm volatile("cp.async.cg.shared.global [%0], [%1], 16;" :: "r"(dst_u32), "l"(src_ptr))
#define CP_COMMIT() asm volatile("cp.async.commit_group;" ::: "memory")
#define CP_WAIT(n)  asm volatile("cp.async.wait_group %0;" :: "n"(n) : "memory")

#define LDMATRIX_X4(r0, r1, r2, r3, addr) \
    asm volatile("ldmatrix.sync.aligned.m8n8.x4.shared.b16 {%0,%1,%2,%3}, [%4];" \
                 : "=r"(r0), "=r"(r1), "=r"(r2), "=r"(r3) : "r"(addr))

#define MMA_BF16(d, a, b0v, b1v) \
    asm volatile("mma.sync.aligned.m16n8k16.row.col.f32.bf16.bf16.f32 " \
                 "{%0,%1,%2,%3},{%4,%5,%6,%7},{%8,%9},{%0,%1,%2,%3};" \
                 : "+f"((d)[0]), "+f"((d)[1]), "+f"((d)[2]), "+f"((d)[3]) \
                 : "r"((a)[0]), "r"((a)[1]), "r"((a)[2]), "r"((a)[3]), \
                   "r"(b0v), "r"(b1v))

// ---------------------------------------------------------------------------
// Prep 1: elementwise split repr -> a_hi/a_lo (bf16)
// ---------------------------------------------------------------------------
__global__ __launch_bounds__(256) void repr_split_kernel(const float* __restrict__ r) {
    size_t i = ((size_t)blockIdx.x * 256 + threadIdx.x) * 4;
    float4 v = *(const float4*)&r[i];
    __nv_bfloat16 hx = __float2bfloat16_rn(v.x);
    __nv_bfloat16 hy = __float2bfloat16_rn(v.y);
    __nv_bfloat16 hz = __float2bfloat16_rn(v.z);
    __nv_bfloat16 hw = __float2bfloat16_rn(v.w);
    __nv_bfloat16 lx = __float2bfloat16_rn(v.x - __bfloat162float(hx));
    __nv_bfloat16 ly = __float2bfloat16_rn(v.y - __bfloat162float(hy));
    __nv_bfloat16 lz = __float2bfloat16_rn(v.z - __bfloat162float(hz));
    __nv_bfloat16 lw = __float2bfloat16_rn(v.w - __bfloat162float(hw));
    __nv_bfloat16 hi4[4] = {hx, hy, hz, hw};
    __nv_bfloat16 lo4[4] = {lx, ly, lz, lw};
    *(uint2*)&g_a_hi[i] = *(uint2*)hi4;
    *(uint2*)&g_a_lo[i] = *(uint2*)lo4;
}

// ---------------------------------------------------------------------------
// Prep 2: W[k][n] -> Wt_hi/Wt_lo [n][k] (transpose + bf16 split)
// ---------------------------------------------------------------------------
__global__ void wt_split_kernel(const float* __restrict__ W) {
    __shared__ float t[32][33];
    int bx = blockIdx.x * 32, by = blockIdx.y * 32;
    int x = threadIdx.x, y0 = threadIdx.y;   // block (32, 8)
#pragma unroll
    for (int i = 0; i < 32; i += 8)
        t[y0 + i][x] = W[(size_t)(by + y0 + i) * HID + bx + x];
    __syncthreads();
#pragma unroll
    for (int i = 0; i < 32; i += 8) {
        float v = t[x][y0 + i];                            // W[by+x][bx+y0+i]
        size_t o = (size_t)(bx + y0 + i) * HID + by + x;   // Wt[n][k]
        __nv_bfloat16 hi = __float2bfloat16_rn(v);
        g_wt_hi[o] = hi;
        g_wt_lo[o] = __float2bfloat16_rn(v - __bfloat162float(hi));
    }
}

// ---------------------------------------------------------------------------
// Kernel 1: bf16x3 GEMM  g_qw[M,N] = repr[M,K] @ W[K,N]
// M=16384, N=K=1024. CTA tile 128x128, KB=32, cp.async double-buffered.
// 8 warps, warp tile 64x32 (mma m16n8k16; 4 m-tiles x 4 n-tiles).
// 3 products: Ah*Bh + Ah*Bl + Al*Bh  (error ~2^-18)
// ---------------------------------------------------------------------------
#define KB   32
#define NCH  (HID / KB)        // 32
#define TPCH 40                // smem row pitch in bf16 (80 bytes, conflict-free)
#define TILE_B  (128 * TPCH * 2)       // 10240 bytes per tile
#define STAGE_B (4 * TILE_B)           // Ah, Al, Bh, Bl  = 40960
#define GEMM_SMEM (2 * STAGE_B)        // 81920

__global__ __launch_bounds__(256, 1) void gemm_bf16x3_kernel() {
    extern __shared__ char sm[];
    const uint32_t smBase = smem_u32(sm);

    const int tid  = threadIdx.x;
    const int w    = tid >> 5;
    const int lane = tid & 31;
    const int wm   = w & 1;        // 0..1  (64-row half)
    const int wn   = w >> 1;       // 0..3  (32-col quarter)
    const int m0   = blockIdx.y * 128;
    const int n0   = blockIdx.x * 128;

    float acc[4][4][4];
#pragma unroll
    for (int i = 0; i < 4; i++)
#pragma unroll
        for (int j = 0; j < 4; j++)
#pragma unroll
            for (int q = 0; q < 4; q++) acc[i][j][q] = 0.f;

    // ---- async tile loader: 4 tiles x (128 rows x 4 x 16B segments) ----
    auto load_chunk = [&](int stage, int c) {
        const int k0 = c * KB;
        const uint32_t sb = smBase + stage * STAGE_B;
#pragma unroll
        for (int i = 0; i < 2; i++) {
            int ch  = tid + i * 256;
            int row = ch >> 2, seg = ch & 3;
            uint32_t doff = (uint32_t)(row * (TPCH * 2) + seg * 16);
            size_t ga = (size_t)(m0 + row) * HID + k0 + seg * 8;
            size_t gb = (size_t)(n0 + row) * HID + k0 + seg * 8;
            CP_ASYNC16(sb + doff,                 &g_a_hi[ga]);
            CP_ASYNC16(sb + TILE_B + doff,        &g_a_lo[ga]);
            CP_ASYNC16(sb + 2 * TILE_B + doff,    &g_wt_hi[gb]);
            CP_ASYNC16(sb + 3 * TILE_B + doff,    &g_wt_lo[gb]);
        }
    };

    load_chunk(0, 0);
    CP_COMMIT();

    for (int c = 0; c < NCH; c++) {
        if (c + 1 < NCH) {
            load_chunk((c + 1) & 1, c + 1);
            CP_COMMIT();
            CP_WAIT(1);
        } else {
            CP_WAIT(0);
        }
        __syncthreads();

        const uint32_t sb = smBase + (c & 1) * STAGE_B;
#pragma unroll
        for (int ks = 0; ks < KB; ks += 16) {
            uint32_t ah[4][4], al[4][4], bh[2][4], bl[2][4];
            const uint32_t cofs = (uint32_t)((ks + ((lane >> 4) << 3)) * 2);
#pragma unroll
            for (int mt = 0; mt < 4; mt++) {
                uint32_t ra = sb + (uint32_t)((wm * 64 + mt * 16 + (lane & 15)) * (TPCH * 2)) + cofs;
                LDMATRIX_X4(ah[mt][0], ah[mt][1], ah[mt][2], ah[mt][3], ra);
                LDMATRIX_X4(al[mt][0], al[mt][1], al[mt][2], al[mt][3], ra + TILE_B);
            }
#pragma unroll
            for (int np = 0; np < 2; np++) {
                uint32_t rb = sb + 2 * TILE_B +
                              (uint32_t)((wn * 32 + np * 16 + (lane & 15)) * (TPCH * 2)) + cofs;
                LDMATRIX_X4(bh[np][0], bh[np][1], bh[np][2], bh[np][3], rb);
                LDMATRIX_X4(bl[np][0], bl[np][1], bl[np][2], bl[np][3], rb + TILE_B);
            }
#pragma unroll
            for (int mt = 0; mt < 4; mt++)
#pragma unroll
                for (int nt = 0; nt < 4; nt++) {
                    const int np = nt >> 1, hp = nt & 1;
                    MMA_BF16(acc[mt][nt], ah[mt], bh[np][hp], bh[np][hp + 2]);
                    MMA_BF16(acc[mt][nt], ah[mt], bl[np][hp], bl[np][hp + 2]);
                    MMA_BF16(acc[mt][nt], al[mt], bh[np][hp], bh[np][hp + 2]);
                }
        }
        __syncthreads();
    }

    // ---- epilogue: direct fp32 stores (8B v2 per fragment row) ----
    const int gid = lane >> 2, tig = lane & 3;
#pragma unroll
    for (int mt = 0; mt < 4; mt++) {
#pragma unroll
        for (int nt = 0; nt < 4; nt++) {
            int r  = m0 + wm * 64 + mt * 16 + gid;
            int cc = n0 + wn * 32 + nt * 8 + tig * 2;
            float2 v0 = {acc[mt][nt][0], acc[mt][nt][1]};
            float2 v1 = {acc[mt][nt][2], acc[mt][nt][3]};
            *(float2*)&g_qw[(size_t)r * HID + cc]       = v0;
            *(float2*)&g_qw[(size_t)(r + 8) * HID + cc] = v1;
        }
    }
}

// ---------------------------------------------------------------------------
// Kernel 2: fused windowed attention (unchanged from R1, known-good)
// ---------------------------------------------------------------------------
#define TQ 64
#define TK 192
#define KC 16
#define SP 193
#define VP 68
#define SMEM_FLOATS (TQ * SP + KC * TQ + KC * TK)

__global__ __launch_bounds__(256) void attn_win_kernel(
    const float* __restrict__ repr, float* __restrict__ out)
{
    extern __shared__ float smem_f[];
    float* Sbuf = smem_f;
    float* Qs   = smem_f + TQ * SP;
    float* Ks   = Qs + KC * TQ;
    float* Vs   = Qs;

    const int b  = blockIdx.y;
    const int q0 = blockIdx.x * TQ;
    const int k0 = q0 - WHALF;

    const float* reprB = repr + (size_t)b * SEQ * HID;
    const float* qwB   = g_qw + (size_t)b * SEQ * HID;
    float*       outB  = out  + (size_t)b * SEQ * HID;

    const int tid = threadIdx.x;
    const int tx = tid % 16;
    const int ty = tid / 16;

    float acc[4][12];
#pragma unroll
    for (int i = 0; i < 4; i++)
#pragma unroll
        for (int j = 0; j < 12; j++) acc[i][j] = 0.f;

    const int qr = tid / 4;
    const int qc = (tid % 4) * 4;

    for (int d0 = 0; d0 < HID; d0 += KC) {
        {
            float4 v = *(const float4*)&qwB[(size_t)(q0 + qr) * HID + d0 + qc];
            Qs[(qc + 0) * TQ + qr] = v.x;
            Qs[(qc + 1) * TQ + qr] = v.y;
            Qs[(qc + 2) * TQ + qr] = v.z;
            Qs[(qc + 3) * TQ + qr] = v.w;
        }
#pragma unroll
        for (int rep = 0; rep < 3; rep++) {
            int kk = qr + rep * 64;
            int j = k0 + kk;
            float4 v = make_float4(0.f, 0.f, 0.f, 0.f);
            if (j >= 0 && j < SEQ)
                v = *(const float4*)&reprB[(size_t)j * HID + d0 + qc];
            Ks[(qc + 0) * TK + kk] = v.x;
            Ks[(qc + 1) * TK + kk] = v.y;
            Ks[(qc + 2) * TK + kk] = v.z;
            Ks[(qc + 3) * TK + kk] = v.w;
        }
        __syncthreads();

#pragma unroll
        for (int k = 0; k < KC; k++) {
            float4 av = *(const float4*)&Qs[k * TQ + ty * 4];
            float a[4] = {av.x, av.y, av.z, av.w};
#pragma unroll
            for (int jj = 0; jj < 12; jj++) {
                float bv = Ks[k * TK + tx + 16 * jj];
                acc[0][jj] += a[0] * bv;
                acc[1][jj] += a[1] * bv;
                acc[2][jj] += a[2] * bv;
                acc[3][jj] += a[3] * bv;
            }
        }
        __syncthreads();
    }

#pragma unroll
    for (int i = 0; i < 4; i++) {
        int row = ty * 4 + i;
#pragma unroll
        for (int jj = 0; jj < 12; jj++) {
            int col = tx + 16 * jj;
            int j = k0 + col;
            int dr = col - row;
            bool valid = (j >= 0) && (j < SEQ) && (dr >= 0) && (dr <= 2 * WHALF);
            Sbuf[row * SP + col] = valid ? acc[i][jj] : NEG_INF;
        }
    }
    __syncthreads();

    if (tid < TQ) {
        float* rowp = &Sbuf[tid * SP];
        float m = NEG_INF;
#pragma unroll 4
        for (int c = 0; c < TK; c++) m = fmaxf(m, rowp[c]);
        float s = 0.f;
#pragma unroll 4
        for (int c = 0; c < TK; c++) {
            float e = __expf(rowp[c] - m);
            rowp[c] = e;
            s += e;
        }
        float inv = 1.f / s;
#pragma unroll 4
        for (int c = 0; c < TK; c++) rowp[c] *= inv;
    }
    __syncthreads();

    for (int dc = 0; dc < HID; dc += 64) {
        float o[4][4] = {};
        for (int kt = 0; kt < TK; kt += KC) {
            __syncthreads();
            {
                int r = tid / 16;
                int c = (tid % 16) * 4;
                int j = k0 + kt + r;
                float4 v = make_float4(0.f, 0.f, 0.f, 0.f);
                if (j >= 0 && j < SEQ)
                    v = *(const float4*)&reprB[(size_t)j * HID + dc + c];
                *(float4*)&Vs[r * VP + c] = v;
            }
            __syncthreads();

#pragma unroll
            for (int k = 0; k < KC; k++) {
                float p0 = Sbuf[(ty * 4 + 0) * SP + kt + k];
                float p1 = Sbuf[(ty * 4 + 1) * SP + kt + k];
                float p2 = Sbuf[(ty * 4 + 2) * SP + kt + k];
                float p3 = Sbuf[(ty * 4 + 3) * SP + kt + k];
                float4 v4 = *(const float4*)&Vs[k * VP + tx * 4];
                float v[4] = {v4.x, v4.y, v4.z, v4.w};
#pragma unroll
                for (int j = 0; j < 4; j++) {
                    o[0][j] += p0 * v[j];
                    o[1][j] += p1 * v[j];
                    o[2][j] += p2 * v[j];
                    o[3][j] += p3 * v[j];
                }
            }
        }
#pragma unroll
        for (int i = 0; i < 4; i++) {
            int q = q0 + ty * 4 + i;
            float4 r4 = *(const float4*)&reprB[(size_t)q * HID + dc + tx * 4];
            float4 ov;
            ov.x = r4.x + fmaxf(o[i][0], 0.f);
            ov.y = r4.y + fmaxf(o[i][1], 0.f);
            ov.z = r4.z + fmaxf(o[i][2], 0.f);
            ov.w = r4.w + fmaxf(o[i][3], 0.f);
            *(float4*)&outB[(size_t)q * HID + dc + tx * 4] = ov;
        }
    }
}

// ---------------------------------------------------------------------------
extern "C" void kernel_launch(void* const* d_in, const int* in_sizes, int n_in,
                              void* d_out, int out_size)
{
    (void)in_sizes; (void)n_in; (void)out_size;
    const float* repr = (const float*)d_in[0];
    const float* W    = (const float*)d_in[1];
    float* out        = (float*)d_out;

    // 0) splits
    repr_split_kernel<<<(M_TOT * HID) / (256 * 4), 256>>>(repr);
    dim3 tb(32, 8), tg(HID / 32, HID / 32);
    wt_split_kernel<<<tg, tb>>>(W);

    // 1) QW = repr @ W  (bf16x3 tensor-core GEMM)
    cudaFuncSetAttribute(gemm_bf16x3_kernel,
                         cudaFuncAttributeMaxDynamicSharedMemorySize, GEMM_SMEM);
    dim3 gg(HID / 128, M_TOT / 128);
    gemm_bf16x3_kernel<<<gg, 256, GEMM_SMEM>>>();

    // 2) fused windowed attention
    cudaFuncSetAttribute(attn_win_kernel,
                         cudaFuncAttributeMaxDynamicSharedMemorySize,
                         SMEM_FLOATS * (int)sizeof(float));
    dim3 ga(SEQ / TQ, BATCH);
    attn_win_kernel<<<ga, 256, SMEM_FLOATS * sizeof(float)>>>(repr, out);
}

// round 4
// speedup vs baseline: 2.2703x; 1.3877x over previous
#include <cuda_runtime.h>
#include <cuda_bf16.h>
#include <cstdint>

#define BATCH 8
#define SEQ   2048
#define HID   1024
#define M_TOT (BATCH * SEQ)        // 16384
#define WHALF 64
#define NEG_INF -1e9f

// Scratch (__device__ globals; no allocation allowed)
__device__ __align__(16) __nv_bfloat16 g_qw_hi[(size_t)M_TOT * HID];  // 32 MB
__device__ __align__(16) __nv_bfloat16 g_qw_lo[(size_t)M_TOT * HID];  // 32 MB
__device__ __align__(16) __nv_bfloat16 g_a_hi[(size_t)M_TOT * HID];   // 32 MB
__device__ __align__(16) __nv_bfloat16 g_a_lo[(size_t)M_TOT * HID];   // 32 MB
__device__ __align__(16) __nv_bfloat16 g_wt_hi[(size_t)HID * HID];    // 2 MB [n][k]
__device__ __align__(16) __nv_bfloat16 g_wt_lo[(size_t)HID * HID];    // 2 MB [n][k]

// ---------------------------------------------------------------------------
// PTX helpers (architecture-neutral, sm_80-level)
// ---------------------------------------------------------------------------
__device__ __forceinline__ uint32_t smem_u32(const void* p) {
    uint32_t a;
    asm("{ .reg .u64 t; cvta.to.shared.u64 t, %1; cvt.u32.u64 %0, t; }" : "=r"(a) : "l"(p));
    return a;
}

#define CP_ASYNC16(dst_u32, src_ptr) \
    asm volatile("cp.async.cg.shared.global [%0], [%1], 16;" :: "r"(dst_u32), "l"(src_ptr))
#define CP_COMMIT() asm volatile("cp.async.commit_group;" ::: "memory")
#define CP_WAIT(n)  asm volatile("cp.async.wait_group %0;" :: "n"(n) : "memory")

#define LDMATRIX_X4(r0, r1, r2, r3, addr) \
    asm volatile("ldmatrix.sync.aligned.m8n8.x4.shared.b16 {%0,%1,%2,%3}, [%4];" \
                 : "=r"(r0), "=r"(r1), "=r"(r2), "=r"(r3) : "r"(addr))
#define LDMATRIX_X4_TRANS(r0, r1, r2, r3, addr) \
    asm volatile("ldmatrix.sync.aligned.m8n8.x4.trans.shared.b16 {%0,%1,%2,%3}, [%4];" \
                 : "=r"(r0), "=r"(r1), "=r"(r2), "=r"(r3) : "r"(addr))

#define MMA_BF16(d, a, b0v, b1v) \
    asm volatile("mma.sync.aligned.m16n8k16.row.col.f32.bf16.bf16.f32 " \
                 "{%0,%1,%2,%3},{%4,%5,%6,%7},{%8,%9},{%0,%1,%2,%3};" \
                 : "+f"((d)[0]), "+f"((d)[1]), "+f"((d)[2]), "+f"((d)[3]) \
                 : "r"((a)[0]), "r"((a)[1]), "r"((a)[2]), "r"((a)[3]), \
                   "r"(b0v), "r"(b1v))

// ---------------------------------------------------------------------------
// Prep 1: repr -> a_hi/a_lo (bf16)
// ---------------------------------------------------------------------------
__global__ __launch_bounds__(256) void repr_split_kernel(const float* __restrict__ r) {
    size_t i = ((size_t)blockIdx.x * 256 + threadIdx.x) * 4;
    float4 v = *(const float4*)&r[i];
    __nv_bfloat16 hx = __float2bfloat16_rn(v.x);
    __nv_bfloat16 hy = __float2bfloat16_rn(v.y);
    __nv_bfloat16 hz = __float2bfloat16_rn(v.z);
    __nv_bfloat16 hw = __float2bfloat16_rn(v.w);
    __nv_bfloat16 lx = __float2bfloat16_rn(v.x - __bfloat162float(hx));
    __nv_bfloat16 ly = __float2bfloat16_rn(v.y - __bfloat162float(hy));
    __nv_bfloat16 lz = __float2bfloat16_rn(v.z - __bfloat162float(hz));
    __nv_bfloat16 lw = __float2bfloat16_rn(v.w - __bfloat162float(hw));
    __nv_bfloat16 hi4[4] = {hx, hy, hz, hw};
    __nv_bfloat16 lo4[4] = {lx, ly, lz, lw};
    *(uint2*)&g_a_hi[i] = *(uint2*)hi4;
    *(uint2*)&g_a_lo[i] = *(uint2*)lo4;
}

// ---------------------------------------------------------------------------
// Prep 2: W[k][n] -> Wt_hi/Wt_lo [n][k]
// ---------------------------------------------------------------------------
__global__ void wt_split_kernel(const float* __restrict__ W) {
    __shared__ float t[32][33];
    int bx = blockIdx.x * 32, by = blockIdx.y * 32;
    int x = threadIdx.x, y0 = threadIdx.y;
#pragma unroll
    for (int i = 0; i < 32; i += 8)
        t[y0 + i][x] = W[(size_t)(by + y0 + i) * HID + bx + x];
    __syncthreads();
#pragma unroll
    for (int i = 0; i < 32; i += 8) {
        float v = t[x][y0 + i];
        size_t o = (size_t)(bx + y0 + i) * HID + by + x;
        __nv_bfloat16 hi = __float2bfloat16_rn(v);
        g_wt_hi[o] = hi;
        g_wt_lo[o] = __float2bfloat16_rn(v - __bfloat162float(hi));
    }
}

// ---------------------------------------------------------------------------
// Kernel 1: bf16x3 GEMM  QW = repr @ W, epilogue stores qw as bf16 hi/lo
// ---------------------------------------------------------------------------
#define KB   32
#define NCH  (HID / KB)
#define TPCH 40
#define TILE_B  (128 * TPCH * 2)
#define STAGE_B (4 * TILE_B)
#define GEMM_SMEM (2 * STAGE_B)

__global__ __launch_bounds__(256, 1) void gemm_bf16x3_kernel() {
    extern __shared__ char sm[];
    const uint32_t smBase = smem_u32(sm);

    const int tid  = threadIdx.x;
    const int w    = tid >> 5;
    const int lane = tid & 31;
    const int wm   = w & 1;
    const int wn   = w >> 1;
    const int m0   = blockIdx.y * 128;
    const int n0   = blockIdx.x * 128;

    float acc[4][4][4];
#pragma unroll
    for (int i = 0; i < 4; i++)
#pragma unroll
        for (int j = 0; j < 4; j++)
#pragma unroll
            for (int q = 0; q < 4; q++) acc[i][j][q] = 0.f;

    auto load_chunk = [&](int stage, int c) {
        const int k0 = c * KB;
        const uint32_t sb = smBase + stage * STAGE_B;
#pragma unroll
        for (int i = 0; i < 2; i++) {
            int ch  = tid + i * 256;
            int row = ch >> 2, seg = ch & 3;
            uint32_t doff = (uint32_t)(row * (TPCH * 2) + seg * 16);
            size_t ga = (size_t)(m0 + row) * HID + k0 + seg * 8;
            size_t gb = (size_t)(n0 + row) * HID + k0 + seg * 8;
            CP_ASYNC16(sb + doff,              &g_a_hi[ga]);
            CP_ASYNC16(sb + TILE_B + doff,     &g_a_lo[ga]);
            CP_ASYNC16(sb + 2 * TILE_B + doff, &g_wt_hi[gb]);
            CP_ASYNC16(sb + 3 * TILE_B + doff, &g_wt_lo[gb]);
        }
    };

    load_chunk(0, 0);
    CP_COMMIT();

    for (int c = 0; c < NCH; c++) {
        if (c + 1 < NCH) {
            load_chunk((c + 1) & 1, c + 1);
            CP_COMMIT();
            CP_WAIT(1);
        } else {
            CP_WAIT(0);
        }
        __syncthreads();

        const uint32_t sb = smBase + (c & 1) * STAGE_B;
#pragma unroll
        for (int ks = 0; ks < KB; ks += 16) {
            uint32_t ah[4][4], al[4][4], bh[2][4], bl[2][4];
            const uint32_t cofs = (uint32_t)((ks + ((lane >> 4) << 3)) * 2);
#pragma unroll
            for (int mt = 0; mt < 4; mt++) {
                uint32_t ra = sb + (uint32_t)((wm * 64 + mt * 16 + (lane & 15)) * (TPCH * 2)) + cofs;
                LDMATRIX_X4(ah[mt][0], ah[mt][1], ah[mt][2], ah[mt][3], ra);
                LDMATRIX_X4(al[mt][0], al[mt][1], al[mt][2], al[mt][3], ra + TILE_B);
            }
#pragma unroll
            for (int np = 0; np < 2; np++) {
                uint32_t rb = sb + 2 * TILE_B +
                              (uint32_t)((wn * 32 + np * 16 + (lane & 15)) * (TPCH * 2)) + cofs;
                LDMATRIX_X4(bh[np][0], bh[np][1], bh[np][2], bh[np][3], rb);
                LDMATRIX_X4(bl[np][0], bl[np][1], bl[np][2], bl[np][3], rb + TILE_B);
            }
#pragma unroll
            for (int mt = 0; mt < 4; mt++)
#pragma unroll
                for (int nt = 0; nt < 4; nt++) {
                    const int np = nt >> 1, hp = nt & 1;
                    MMA_BF16(acc[mt][nt], ah[mt], bh[np][hp], bh[np][hp + 2]);
                    MMA_BF16(acc[mt][nt], ah[mt], bl[np][hp], bl[np][hp + 2]);
                    MMA_BF16(acc[mt][nt], al[mt], bh[np][hp], bh[np][hp + 2]);
                }
        }
        __syncthreads();
    }

    // epilogue: split each fp32 into bf16 hi/lo and store packed pairs
    const int gid = lane >> 2, tig = lane & 3;
#pragma unroll
    for (int mt = 0; mt < 4; mt++) {
#pragma unroll
        for (int nt = 0; nt < 4; nt++) {
#pragma unroll
            for (int h = 0; h < 2; h++) {
                int r  = m0 + wm * 64 + mt * 16 + gid + h * 8;
                int cc = n0 + wn * 32 + nt * 8 + tig * 2;
                float v0 = acc[mt][nt][h * 2 + 0];
                float v1 = acc[mt][nt][h * 2 + 1];
                __nv_bfloat16 h0 = __float2bfloat16_rn(v0);
                __nv_bfloat16 h1 = __float2bfloat16_rn(v1);
                __nv_bfloat16 l0 = __float2bfloat16_rn(v0 - __bfloat162float(h0));
                __nv_bfloat16 l1 = __float2bfloat16_rn(v1 - __bfloat162float(h1));
                __nv_bfloat16 hp2[2] = {h0, h1};
                __nv_bfloat16 lp2[2] = {l0, l1};
                *(uint32_t*)&g_qw_hi[(size_t)r * HID + cc] = *(uint32_t*)hp2;
                *(uint32_t*)&g_qw_lo[(size_t)r * HID + cc] = *(uint32_t*)lp2;
            }
        }
    }
}

// ---------------------------------------------------------------------------
// Kernel 2: tensor-core fused windowed attention
// Block: (batch, 64-query tile). Band = 192 keys. 256 threads, 8 warps.
// Phase 1: S[64,192] = Q·K^T (bf16x3, K=1024, cp.async double-buffered)
// Phase 2: warp-parallel softmax -> P split hi/lo bf16
// Phase 3: RA[64,1024] = P·V (bf16x3, ldmatrix.trans for V), residual+relu
// ---------------------------------------------------------------------------
#define ATQ 64
#define ATK 192
#define APITCH 40            // bf16 pitch, phase-1 tiles (80 B rows)
#define PPITCH 200           // pitch: fp32 for S, bf16 for P
#define VPITCH 136           // bf16 pitch for V tiles (272 B rows)

#define A_STAGE 40960        // Qh 0 | Ql 5120 | Kh 10240 | Kl 25600
#define A_QH 0
#define A_QL 5120
#define A_KH 10240
#define A_KL 25600
#define RB_OFF 81920         // region B: S fp32 [64][200] (51200 B)
#define P_PH 0               // P over region A (phase-1 stages dead)
#define P_PL 25600
#define V_VH 0               // V over region B (S dead)
#define V_VL 17408
#define ATTN_SMEM (81920 + 51200)

__global__ __launch_bounds__(256, 1) void attn_tc_kernel(
    const float* __restrict__ repr, float* __restrict__ out)
{
    extern __shared__ char sm[];
    const uint32_t smb = smem_u32(sm);

    const int tid  = threadIdx.x;
    const int w    = tid >> 5;
    const int lane = tid & 31;
    const int gid  = lane >> 2, tig = lane & 3;
    const int wm   = w & 3;          // 4 m-groups of 16 rows
    const int wk   = w >> 2;         // phase-1: 2 col-groups of 96
    const int wd   = w >> 2;         // phase-3: 2 d-halves of 64

    const int b  = blockIdx.y;
    const int q0 = blockIdx.x * ATQ;
    const int k0 = q0 - WHALF;
    const size_t rowbase = (size_t)b * SEQ;

    // ---------------- Phase 1: S = Q·K^T --------------------------------
    auto load_qk = [&](int stage, int c) {
        const int kd = c * KB;
        const uint32_t sb = smb + stage * A_STAGE;
        {
            int row = tid >> 2, seg = tid & 3;
            uint32_t off = (uint32_t)(row * (APITCH * 2) + seg * 16);
            size_t ga = (rowbase + q0 + row) * HID + kd + seg * 8;
            CP_ASYNC16(sb + A_QH + off, &g_qw_hi[ga]);
            CP_ASYNC16(sb + A_QL + off, &g_qw_lo[ga]);
        }
#pragma unroll
        for (int rep = 0; rep < 3; rep++) {
            int idx = tid + rep * 256;
            int row = idx >> 2, seg = idx & 3;
            int j = k0 + row;
            j = j < 0 ? 0 : (j >= SEQ ? SEQ - 1 : j);   // clamp; masked later
            uint32_t off = (uint32_t)(row * (APITCH * 2) + seg * 16);
            size_t ga = (rowbase + j) * HID + kd + seg * 8;
            CP_ASYNC16(sb + A_KH + off, &g_a_hi[ga]);
            CP_ASYNC16(sb + A_KL + off, &g_a_lo[ga]);
        }
    };

    float acc[12][4];
#pragma unroll
    for (int i = 0; i < 12; i++)
#pragma unroll
        for (int q = 0; q < 4; q++) acc[i][q] = 0.f;

    load_qk(0, 0);
    CP_COMMIT();

    for (int c = 0; c < NCH; c++) {
        if (c + 1 < NCH) { load_qk((c + 1) & 1, c + 1); CP_COMMIT(); CP_WAIT(1); }
        else             { CP_WAIT(0); }
        __syncthreads();
        const uint32_t sb = smb + (c & 1) * A_STAGE;
#pragma unroll
        for (int ks = 0; ks < 2; ks++) {
            const uint32_t cofs = (uint32_t)((ks * 16 + ((lane >> 4) << 3)) * 2);
            uint32_t ah[4], al[4];
            uint32_t ra = sb + A_QH + (uint32_t)((wm * 16 + (lane & 15)) * (APITCH * 2)) + cofs;
            LDMATRIX_X4(ah[0], ah[1], ah[2], ah[3], ra);
            LDMATRIX_X4(al[0], al[1], al[2], al[3], ra + (A_QL - A_QH));
#pragma unroll
            for (int p = 0; p < 6; p++) {
                uint32_t bh[4], bl[4];
                uint32_t rb = sb + A_KH +
                    (uint32_t)((wk * 96 + p * 16 + (lane & 15)) * (APITCH * 2)) + cofs;
                LDMATRIX_X4(bh[0], bh[1], bh[2], bh[3], rb);
                LDMATRIX_X4(bl[0], bl[1], bl[2], bl[3], rb + (A_KL - A_KH));
#pragma unroll
                for (int hp = 0; hp < 2; hp++) {
                    int nt = p * 2 + hp;
                    MMA_BF16(acc[nt], ah, bh[hp], bh[hp + 2]);
                    MMA_BF16(acc[nt], ah, bl[hp], bl[hp + 2]);
                    MMA_BF16(acc[nt], al, bh[hp], bh[hp + 2]);
                }
            }
        }
        __syncthreads();
    }

    // store S with window mask
    float* Sb = (float*)(sm + RB_OFF);
#pragma unroll
    for (int nt = 0; nt < 12; nt++) {
#pragma unroll
        for (int h = 0; h < 2; h++) {
            int row = wm * 16 + gid + h * 8;
            int col = wk * 96 + nt * 8 + tig * 2;
#pragma unroll
            for (int e = 0; e < 2; e++) {
                int cc = col + e;
                int j = k0 + cc, dr = cc - row;
                bool v = (j >= 0) && (j < SEQ) && (dr >= 0) && (dr <= 2 * WHALF);
                Sb[row * PPITCH + cc] = v ? acc[nt][h * 2 + e] : NEG_INF;
            }
        }
    }
    __syncthreads();

    // ---------------- Phase 2: softmax -> P hi/lo -----------------------
    {
        int row = tid >> 2, seg = tid & 3;
        float* rp = &Sb[row * PPITCH + seg * 48];
        float m = NEG_INF;
#pragma unroll 8
        for (int c = 0; c < 48; c++) m = fmaxf(m, rp[c]);
        m = fmaxf(m, __shfl_xor_sync(0xffffffffu, m, 1));
        m = fmaxf(m, __shfl_xor_sync(0xffffffffu, m, 2));
        float s = 0.f;
#pragma unroll 8
        for (int c = 0; c < 48; c++) {
            float e = __expf(rp[c] - m);
            rp[c] = e;
            s += e;
        }
        s += __shfl_xor_sync(0xffffffffu, s, 1);
        s += __shfl_xor_sync(0xffffffffu, s, 2);
        float inv = 1.f / s;
        __nv_bfloat16* Ph = (__nv_bfloat16*)(sm + P_PH);
        __nv_bfloat16* Pl = (__nv_bfloat16*)(sm + P_PL);
#pragma unroll 8
        for (int c = 0; c < 48; c++) {
            float p = rp[c] * inv;
            __nv_bfloat16 hh = __float2bfloat16_rn(p);
            Ph[row * PPITCH + seg * 48 + c] = hh;
            Pl[row * PPITCH + seg * 48 + c] = __float2bfloat16_rn(p - __bfloat162float(hh));
        }
    }
    __syncthreads();

    // ---------------- Phase 3: RA = P·V, residual + relu ----------------
    for (int dc = 0; dc < 8; dc++) {
        const int d0 = dc * 128;
        float o[8][4];
#pragma unroll
        for (int i = 0; i < 8; i++)
#pragma unroll
            for (int q = 0; q < 4; q++) o[i][q] = 0.f;

        for (int kt = 0; kt < 3; kt++) {
            __syncthreads();   // protect V buffer
#pragma unroll
            for (int rep = 0; rep < 4; rep++) {
                int idx = tid + rep * 256;
                int vr = idx >> 4, seg = idx & 15;
                int j = k0 + kt * 64 + vr;
                j = j < 0 ? 0 : (j >= SEQ ? SEQ - 1 : j);  // clamp; P=0 there
                uint32_t off = (uint32_t)(vr * (VPITCH * 2) + seg * 16);
                size_t ga = (rowbase + j) * HID + d0 + seg * 8;
                CP_ASYNC16(smb + RB_OFF + V_VH + off, &g_a_hi[ga]);
                CP_ASYNC16(smb + RB_OFF + V_VL + off, &g_a_lo[ga]);
            }
            CP_COMMIT(); CP_WAIT(0);
            __syncthreads();

#pragma unroll
            for (int ks = 0; ks < 4; ks++) {
                int kk = kt * 64 + ks * 16;
                uint32_t ah[4], al[4];
                uint32_t ra = smb + P_PH +
                    (uint32_t)((wm * 16 + (lane & 15)) * (PPITCH * 2)) +
                    (uint32_t)((kk + ((lane >> 4) << 3)) * 2);
                LDMATRIX_X4(ah[0], ah[1], ah[2], ah[3], ra);
                LDMATRIX_X4(al[0], al[1], al[2], al[3], ra + (P_PL - P_PH));
#pragma unroll
                for (int p = 0; p < 4; p++) {
                    uint32_t bh[4], bl[4];
                    uint32_t rb = smb + RB_OFF + V_VH +
                        (uint32_t)((ks * 16 + (lane & 15)) * (VPITCH * 2)) +
                        (uint32_t)((wd * 64 + p * 16 + ((lane >> 4) << 3)) * 2);
                    LDMATRIX_X4_TRANS(bh[0], bh[1], bh[2], bh[3], rb);
                    LDMATRIX_X4_TRANS(bl[0], bl[1], bl[2], bl[3], rb + (V_VL - V_VH));
#pragma unroll
                    for (int hp = 0; hp < 2; hp++) {
                        int nt = p * 2 + hp;
                        MMA_BF16(o[nt], ah, bh[2 * hp], bh[2 * hp + 1]);
                        MMA_BF16(o[nt], ah, bl[2 * hp], bl[2 * hp + 1]);
                        MMA_BF16(o[nt], al, bh[2 * hp], bh[2 * hp + 1]);
                    }
                }
            }
        }

        // epilogue for this 128-col chunk
#pragma unroll
        for (int nt = 0; nt < 8; nt++) {
#pragma unroll
            for (int h = 0; h < 2; h++) {
                int r = q0 + wm * 16 + gid + h * 8;
                int col = d0 + wd * 64 + nt * 8 + tig * 2;
                const float2 rv = *(const float2*)&repr[(rowbase + r) * HID + col];
                float2 ov;
                ov.x = rv.x + fmaxf(o[nt][h * 2 + 0], 0.f);
                ov.y = rv.y + fmaxf(o[nt][h * 2 + 1], 0.f);
                *(float2*)&out[(rowbase + r) * HID + col] = ov;
            }
        }
    }
}

// ---------------------------------------------------------------------------
extern "C" void kernel_launch(void* const* d_in, const int* in_sizes, int n_in,
                              void* d_out, int out_size)
{
    (void)in_sizes; (void)n_in; (void)out_size;
    const float* repr = (const float*)d_in[0];
    const float* W    = (const float*)d_in[1];
    float* out        = (float*)d_out;

    // 0) splits
    repr_split_kernel<<<(M_TOT * HID) / (256 * 4), 256>>>(repr);
    dim3 tb(32, 8), tg(HID / 32, HID / 32);
    wt_split_kernel<<<tg, tb>>>(W);

    // 1) QW = repr @ W  (bf16x3 tensor-core GEMM, bf16 hi/lo output)
    cudaFuncSetAttribute(gemm_bf16x3_kernel,
                         cudaFuncAttributeMaxDynamicSharedMemorySize, GEMM_SMEM);
    dim3 gg(HID / 128, M_TOT / 128);
    gemm_bf16x3_kernel<<<gg, 256, GEMM_SMEM>>>();

    // 2) tensor-core fused windowed attention
    cudaFuncSetAttribute(attn_tc_kernel,
                         cudaFuncAttributeMaxDynamicSharedMemorySize, ATTN_SMEM);
    dim3 ga(SEQ / ATQ, BATCH);
    attn_tc_kernel<<<ga, 256, ATTN_SMEM>>>(repr, out);
}

// round 5
// speedup vs baseline: 2.5391x; 1.1184x over previous
#include <cuda_runtime.h>
#include <cuda_bf16.h>
#include <cstdint>

#define BATCH 8
#define SEQ   2048
#define HID   1024
#define M_TOT (BATCH * SEQ)        // 16384
#define WHALF 64
#define NEG_INF -1e9f

// Scratch (__device__ globals; no allocation allowed)
__device__ __align__(16) __nv_bfloat16 g_qw_hi[(size_t)M_TOT * HID];
__device__ __align__(16) __nv_bfloat16 g_qw_lo[(size_t)M_TOT * HID];
__device__ __align__(16) __nv_bfloat16 g_a_hi[(size_t)M_TOT * HID];
__device__ __align__(16) __nv_bfloat16 g_a_lo[(size_t)M_TOT * HID];
__device__ __align__(16) __nv_bfloat16 g_wt_hi[(size_t)HID * HID];
__device__ __align__(16) __nv_bfloat16 g_wt_lo[(size_t)HID * HID];

// ---------------------------------------------------------------------------
// PTX helpers (architecture-neutral, sm_80-level)
// ---------------------------------------------------------------------------
__device__ __forceinline__ uint32_t smem_u32(const void* p) {
    uint32_t a;
    asm("{ .reg .u64 t; cvta.to.shared.u64 t, %1; cvt.u32.u64 %0, t; }" : "=r"(a) : "l"(p));
    return a;
}

#define CP_ASYNC16(dst_u32, src_ptr) \
    asm volatile("cp.async.cg.shared.global [%0], [%1], 16;" :: "r"(dst_u32), "l"(src_ptr))
#define CP_COMMIT() asm volatile("cp.async.commit_group;" ::: "memory")
#define CP_WAIT(n)  asm volatile("cp.async.wait_group %0;" :: "n"(n) : "memory")

#define LDMATRIX_X4(r0, r1, r2, r3, addr) \
    asm volatile("ldmatrix.sync.aligned.m8n8.x4.shared.b16 {%0,%1,%2,%3}, [%4];" \
                 : "=r"(r0), "=r"(r1), "=r"(r2), "=r"(r3) : "r"(addr))
#define LDMATRIX_X4_TRANS(r0, r1, r2, r3, addr) \
    asm volatile("ldmatrix.sync.aligned.m8n8.x4.trans.shared.b16 {%0,%1,%2,%3}, [%4];" \
                 : "=r"(r0), "=r"(r1), "=r"(r2), "=r"(r3) : "r"(addr))

#define MMA_BF16(d, a, b0v, b1v) \
    asm volatile("mma.sync.aligned.m16n8k16.row.col.f32.bf16.bf16.f32 " \
                 "{%0,%1,%2,%3},{%4,%5,%6,%7},{%8,%9},{%0,%1,%2,%3};" \
                 : "+f"((d)[0]), "+f"((d)[1]), "+f"((d)[2]), "+f"((d)[3]) \
                 : "r"((a)[0]), "r"((a)[1]), "r"((a)[2]), "r"((a)[3]), \
                   "r"(b0v), "r"(b1v))

__device__ __forceinline__ void split_pack(float a, float b, uint32_t& hi, uint32_t& lo) {
    __nv_bfloat16 ha = __float2bfloat16_rn(a);
    __nv_bfloat16 hb = __float2bfloat16_rn(b);
    __nv_bfloat16 la = __float2bfloat16_rn(a - __bfloat162float(ha));
    __nv_bfloat16 lb = __float2bfloat16_rn(b - __bfloat162float(hb));
    __nv_bfloat16 hp[2] = {ha, hb};
    __nv_bfloat16 lp[2] = {la, lb};
    hi = *(uint32_t*)hp;
    lo = *(uint32_t*)lp;
}

// ---------------------------------------------------------------------------
// Prep 1: repr -> a_hi/a_lo (bf16)
// ---------------------------------------------------------------------------
__global__ __launch_bounds__(256) void repr_split_kernel(const float* __restrict__ r) {
    size_t i = ((size_t)blockIdx.x * 256 + threadIdx.x) * 4;
    float4 v = *(const float4*)&r[i];
    uint32_t h0, l0, h1, l1;
    split_pack(v.x, v.y, h0, l0);
    split_pack(v.z, v.w, h1, l1);
    uint2 hh = {h0, h1}, ll = {l0, l1};
    *(uint2*)&g_a_hi[i] = hh;
    *(uint2*)&g_a_lo[i] = ll;
}

// ---------------------------------------------------------------------------
// Prep 2: W[k][n] -> Wt_hi/Wt_lo [n][k]
// ---------------------------------------------------------------------------
__global__ void wt_split_kernel(const float* __restrict__ W) {
    __shared__ float t[32][33];
    int bx = blockIdx.x * 32, by = blockIdx.y * 32;
    int x = threadIdx.x, y0 = threadIdx.y;
#pragma unroll
    for (int i = 0; i < 32; i += 8)
        t[y0 + i][x] = W[(size_t)(by + y0 + i) * HID + bx + x];
    __syncthreads();
#pragma unroll
    for (int i = 0; i < 32; i += 8) {
        float v = t[x][y0 + i];
        size_t o = (size_t)(bx + y0 + i) * HID + by + x;
        __nv_bfloat16 hi = __float2bfloat16_rn(v);
        g_wt_hi[o] = hi;
        g_wt_lo[o] = __float2bfloat16_rn(v - __bfloat162float(hi));
    }
}

// ---------------------------------------------------------------------------
// Kernel 1: bf16x3 GEMM  QW = repr @ W, bf16 hi/lo output  (R4 + occupancy 2)
// ---------------------------------------------------------------------------
#define KB   32
#define NCH  (HID / KB)
#define TPCH 40
#define TILE_B  (128 * TPCH * 2)
#define STAGE_B (4 * TILE_B)
#define GEMM_SMEM (2 * STAGE_B)

__global__ __launch_bounds__(256, 2) void gemm_bf16x3_kernel() {
    extern __shared__ char sm[];
    const uint32_t smBase = smem_u32(sm);

    const int tid  = threadIdx.x;
    const int w    = tid >> 5;
    const int lane = tid & 31;
    const int wm   = w & 1;
    const int wn   = w >> 1;
    const int m0   = blockIdx.y * 128;
    const int n0   = blockIdx.x * 128;

    float acc[4][4][4];
#pragma unroll
    for (int i = 0; i < 4; i++)
#pragma unroll
        for (int j = 0; j < 4; j++)
#pragma unroll
            for (int q = 0; q < 4; q++) acc[i][j][q] = 0.f;

    auto load_chunk = [&](int stage, int c) {
        const int k0 = c * KB;
        const uint32_t sb = smBase + stage * STAGE_B;
#pragma unroll
        for (int i = 0; i < 2; i++) {
            int ch  = tid + i * 256;
            int row = ch >> 2, seg = ch & 3;
            uint32_t doff = (uint32_t)(row * (TPCH * 2) + seg * 16);
            size_t ga = (size_t)(m0 + row) * HID + k0 + seg * 8;
            size_t gb = (size_t)(n0 + row) * HID + k0 + seg * 8;
            CP_ASYNC16(sb + doff,              &g_a_hi[ga]);
            CP_ASYNC16(sb + TILE_B + doff,     &g_a_lo[ga]);
            CP_ASYNC16(sb + 2 * TILE_B + doff, &g_wt_hi[gb]);
            CP_ASYNC16(sb + 3 * TILE_B + doff, &g_wt_lo[gb]);
        }
    };

    load_chunk(0, 0);
    CP_COMMIT();

    for (int c = 0; c < NCH; c++) {
        if (c + 1 < NCH) {
            load_chunk((c + 1) & 1, c + 1);
            CP_COMMIT();
            CP_WAIT(1);
        } else {
            CP_WAIT(0);
        }
        __syncthreads();

        const uint32_t sb = smBase + (c & 1) * STAGE_B;
#pragma unroll
        for (int ks = 0; ks < KB; ks += 16) {
            uint32_t ah[4][4], al[4][4], bh[2][4], bl[2][4];
            const uint32_t cofs = (uint32_t)((ks + ((lane >> 4) << 3)) * 2);
#pragma unroll
            for (int mt = 0; mt < 4; mt++) {
                uint32_t ra = sb + (uint32_t)((wm * 64 + mt * 16 + (lane & 15)) * (TPCH * 2)) + cofs;
                LDMATRIX_X4(ah[mt][0], ah[mt][1], ah[mt][2], ah[mt][3], ra);
                LDMATRIX_X4(al[mt][0], al[mt][1], al[mt][2], al[mt][3], ra + TILE_B);
            }
#pragma unroll
            for (int np = 0; np < 2; np++) {
                uint32_t rb = sb + 2 * TILE_B +
                              (uint32_t)((wn * 32 + np * 16 + (lane & 15)) * (TPCH * 2)) + cofs;
                LDMATRIX_X4(bh[np][0], bh[np][1], bh[np][2], bh[np][3], rb);
                LDMATRIX_X4(bl[np][0], bl[np][1], bl[np][2], bl[np][3], rb + TILE_B);
            }
#pragma unroll
            for (int mt = 0; mt < 4; mt++)
#pragma unroll
                for (int nt = 0; nt < 4; nt++) {
                    const int np = nt >> 1, hp = nt & 1;
                    MMA_BF16(acc[mt][nt], ah[mt], bh[np][hp], bh[np][hp + 2]);
                    MMA_BF16(acc[mt][nt], ah[mt], bl[np][hp], bl[np][hp + 2]);
                    MMA_BF16(acc[mt][nt], al[mt], bh[np][hp], bh[np][hp + 2]);
                }
        }
        __syncthreads();
    }

    const int gid = lane >> 2, tig = lane & 3;
#pragma unroll
    for (int mt = 0; mt < 4; mt++) {
#pragma unroll
        for (int nt = 0; nt < 4; nt++) {
#pragma unroll
            for (int h = 0; h < 2; h++) {
                int r  = m0 + wm * 64 + mt * 16 + gid + h * 8;
                int cc = n0 + wn * 32 + nt * 8 + tig * 2;
                uint32_t hp2, lp2;
                split_pack(acc[mt][nt][h * 2 + 0], acc[mt][nt][h * 2 + 1], hp2, lp2);
                *(uint32_t*)&g_qw_hi[(size_t)r * HID + cc] = hp2;
                *(uint32_t*)&g_qw_lo[(size_t)r * HID + cc] = lp2;
            }
        }
    }
}

// ---------------------------------------------------------------------------
// Kernel 2: tensor-core windowed attention, register-resident P
// Block: (batch, 64-query tile), 256 thr / 8 warps: wm = w&3 (16-row group),
// wk = w>>2 (96-key half). Phase 1: S frags in regs (bf16x3 over K=1024).
// Phase 2: softmax on frags (shfl + tiny smem exchange), P hi/lo frags in regs.
// Phase 3: dc-chunks of 32 cols; V double-buffered; each wk-half computes
// partial O over its 96 keys; wk=1 writes partials to smem; wk=0 adds,
// applies residual+relu, stores.
// ---------------------------------------------------------------------------
#define APITCH 40                    // bf16 pitch (80 B rows)
#define AQ_B   (64 * APITCH * 2)     // 5120
#define AK_B   (192 * APITCH * 2)    // 15360
#define A_STG  (2 * AQ_B + 2 * AK_B) // 40960: Qh | Ql | Kh | Kl
#define VPITCH 40                    // bf16 pitch for 32-col V tiles
#define V_B    (192 * VPITCH * 2)    // 15360
#define V_STG  (2 * V_B)             // 30720: Vh | Vl
#define OBUF_OFF  61440              // 64 x 34 fp32 = 8704
#define STAT_OFF  81920              // max[128] + sum[128] fp32 = 1024
#define ATTN_SMEM (STAT_OFF + 1024)  // 82944
#define DCW 32
#define NDC (HID / DCW)              // 32

__global__ __launch_bounds__(256, 2) void attn_tc_kernel(
    const float* __restrict__ repr, float* __restrict__ out)
{
    extern __shared__ char sm[];
    const uint32_t smb = smem_u32(sm);

    const int tid  = threadIdx.x;
    const int w    = tid >> 5;
    const int lane = tid & 31;
    const int gid  = lane >> 2, tig = lane & 3;
    const int wm   = w & 3;
    const int wk   = w >> 2;

    const int b  = blockIdx.y;
    const int q0 = blockIdx.x * 64;
    const int k0 = q0 - WHALF;
    const size_t rowbase = (size_t)b * SEQ;

    // ---------------- Phase 1: S = Q·K^T (frags in regs) -----------------
    auto load_qk = [&](int stage, int c) {
        const int kd = c * KB;
        const uint32_t sb = smb + stage * A_STG;
        {
            int row = tid >> 2, seg = tid & 3;
            uint32_t off = (uint32_t)(row * (APITCH * 2) + seg * 16);
            size_t ga = (rowbase + q0 + row) * HID + kd + seg * 8;
            CP_ASYNC16(sb + off,        &g_qw_hi[ga]);
            CP_ASYNC16(sb + AQ_B + off, &g_qw_lo[ga]);
        }
#pragma unroll
        for (int rep = 0; rep < 3; rep++) {
            int idx = tid + rep * 256;
            int row = idx >> 2, seg = idx & 3;
            int j = k0 + row;
            j = j < 0 ? 0 : (j >= SEQ ? SEQ - 1 : j);   // clamp; masked later
            uint32_t off = (uint32_t)(row * (APITCH * 2) + seg * 16);
            size_t ga = (rowbase + j) * HID + kd + seg * 8;
            CP_ASYNC16(sb + 2 * AQ_B + off,        &g_a_hi[ga]);
            CP_ASYNC16(sb + 2 * AQ_B + AK_B + off, &g_a_lo[ga]);
        }
    };

    float acc[12][4];
#pragma unroll
    for (int i = 0; i < 12; i++)
#pragma unroll
        for (int q = 0; q < 4; q++) acc[i][q] = 0.f;

    load_qk(0, 0);
    CP_COMMIT();

    for (int c = 0; c < NCH; c++) {
        if (c + 1 < NCH) { load_qk((c + 1) & 1, c + 1); CP_COMMIT(); CP_WAIT(1); }
        else             { CP_WAIT(0); }
        __syncthreads();
        const uint32_t sb = smb + (c & 1) * A_STG;
#pragma unroll
        for (int ks = 0; ks < 2; ks++) {
            const uint32_t cofs = (uint32_t)((ks * 16 + ((lane >> 4) << 3)) * 2);
            uint32_t ah[4], al[4];
            uint32_t ra = sb + (uint32_t)((wm * 16 + (lane & 15)) * (APITCH * 2)) + cofs;
            LDMATRIX_X4(ah[0], ah[1], ah[2], ah[3], ra);
            LDMATRIX_X4(al[0], al[1], al[2], al[3], ra + AQ_B);
#pragma unroll
            for (int p = 0; p < 6; p++) {
                uint32_t bh[4], bl[4];
                uint32_t rb = sb + 2 * AQ_B +
                    (uint32_t)((wk * 96 + p * 16 + (lane & 15)) * (APITCH * 2)) + cofs;
                LDMATRIX_X4(bh[0], bh[1], bh[2], bh[3], rb);
                LDMATRIX_X4(bl[0], bl[1], bl[2], bl[3], rb + AK_B);
#pragma unroll
                for (int hp = 0; hp < 2; hp++) {
                    int nt = p * 2 + hp;
                    MMA_BF16(acc[nt], ah, bh[hp], bh[hp + 2]);
                    MMA_BF16(acc[nt], ah, bl[hp], bl[hp + 2]);
                    MMA_BF16(acc[nt], al, bh[hp], bh[hp + 2]);
                }
            }
        }
        __syncthreads();
    }

    // ---------------- Phase 2: softmax on register fragments -------------
    // mask
#pragma unroll
    for (int nt = 0; nt < 12; nt++) {
#pragma unroll
        for (int h = 0; h < 2; h++) {
            int row = wm * 16 + gid + h * 8;
#pragma unroll
            for (int e = 0; e < 2; e++) {
                int col = wk * 96 + nt * 8 + tig * 2 + e;
                int j = k0 + col, dr = col - row;
                if (!((j >= 0) && (j < SEQ) && (dr >= 0) && (dr <= 2 * WHALF)))
                    acc[nt][h * 2 + e] = NEG_INF;
            }
        }
    }

    float* statb = (float*)(sm + STAT_OFF);
    float mrow[2] = {NEG_INF, NEG_INF};
#pragma unroll
    for (int nt = 0; nt < 12; nt++) {
        mrow[0] = fmaxf(mrow[0], fmaxf(acc[nt][0], acc[nt][1]));
        mrow[1] = fmaxf(mrow[1], fmaxf(acc[nt][2], acc[nt][3]));
    }
#pragma unroll
    for (int h = 0; h < 2; h++) {
        mrow[h] = fmaxf(mrow[h], __shfl_xor_sync(0xffffffffu, mrow[h], 1));
        mrow[h] = fmaxf(mrow[h], __shfl_xor_sync(0xffffffffu, mrow[h], 2));
    }
    if (tig == 0) {
        statb[wk * 64 + wm * 16 + gid]     = mrow[0];
        statb[wk * 64 + wm * 16 + gid + 8] = mrow[1];
    }
    __syncthreads();
    mrow[0] = fmaxf(mrow[0], statb[(1 - wk) * 64 + wm * 16 + gid]);
    mrow[1] = fmaxf(mrow[1], statb[(1 - wk) * 64 + wm * 16 + gid + 8]);

    float srow[2] = {0.f, 0.f};
#pragma unroll
    for (int nt = 0; nt < 12; nt++) {
#pragma unroll
        for (int h = 0; h < 2; h++) {
#pragma unroll
            for (int e = 0; e < 2; e++) {
                float ex = __expf(acc[nt][h * 2 + e] - mrow[h]);
                acc[nt][h * 2 + e] = ex;
                srow[h] += ex;
            }
        }
    }
#pragma unroll
    for (int h = 0; h < 2; h++) {
        srow[h] += __shfl_xor_sync(0xffffffffu, srow[h], 1);
        srow[h] += __shfl_xor_sync(0xffffffffu, srow[h], 2);
    }
    float* sumb = statb + 128;
    if (tig == 0) {
        sumb[wk * 64 + wm * 16 + gid]     = srow[0];
        sumb[wk * 64 + wm * 16 + gid + 8] = srow[1];
    }
    __syncthreads();
    float inv0 = 1.f / (srow[0] + sumb[(1 - wk) * 64 + wm * 16 + gid]);
    float inv1 = 1.f / (srow[1] + sumb[(1 - wk) * 64 + wm * 16 + gid + 8]);

    // build P hi/lo A-fragments for this warp's 96-key half (6 k-tiles)
    uint32_t ph[6][4], pl[6][4];
#pragma unroll
    for (int t = 0; t < 6; t++) {
        split_pack(acc[2 * t][0] * inv0,     acc[2 * t][1] * inv0,     ph[t][0], pl[t][0]);
        split_pack(acc[2 * t][2] * inv1,     acc[2 * t][3] * inv1,     ph[t][1], pl[t][1]);
        split_pack(acc[2 * t + 1][0] * inv0, acc[2 * t + 1][1] * inv0, ph[t][2], pl[t][2]);
        split_pack(acc[2 * t + 1][2] * inv1, acc[2 * t + 1][3] * inv1, ph[t][3], pl[t][3]);
    }
    __syncthreads();

    // ---------------- Phase 3: O = P·V, dc-chunks of 32, double-buffered --
    auto load_v = [&](int stage, int d) {
        const int d0 = d * DCW;
        const uint32_t sb = smb + stage * V_STG;
#pragma unroll
        for (int rep = 0; rep < 6; rep++) {
            int idx = tid + rep * 256;
            int vr = idx >> 3, seg = idx & 3, buf = (idx >> 2) & 1;
            int j = k0 + vr;
            j = j < 0 ? 0 : (j >= SEQ ? SEQ - 1 : j);   // clamp; P=0 there
            uint32_t off = (uint32_t)(vr * (VPITCH * 2) + seg * 16);
            size_t ga = (rowbase + j) * HID + d0 + seg * 8;
            if (buf == 0) CP_ASYNC16(sb + off,       &g_a_hi[ga]);
            else          CP_ASYNC16(sb + V_B + off, &g_a_lo[ga]);
        }
    };

    load_v(0, 0);
    CP_COMMIT();

    float* ob = (float*)(sm + OBUF_OFF);

    for (int d = 0; d < NDC; d++) {
        if (d + 1 < NDC) { load_v((d + 1) & 1, d + 1); CP_COMMIT(); CP_WAIT(1); }
        else             { CP_WAIT(0); }
        __syncthreads();
        const uint32_t vb = smb + (d & 1) * V_STG;

        float o[4][4];
#pragma unroll
        for (int i = 0; i < 4; i++)
#pragma unroll
            for (int q = 0; q < 4; q++) o[i][q] = 0.f;

#pragma unroll
        for (int t = 0; t < 6; t++) {
            const int krow = wk * 96 + t * 16;
#pragma unroll
            for (int p = 0; p < 2; p++) {
                uint32_t bh[4], bl[4];
                uint32_t rb = vb + (uint32_t)((krow + (lane & 15)) * (VPITCH * 2)) +
                              (uint32_t)((p * 16 + ((lane >> 4) << 3)) * 2);
                LDMATRIX_X4_TRANS(bh[0], bh[1], bh[2], bh[3], rb);
                LDMATRIX_X4_TRANS(bl[0], bl[1], bl[2], bl[3], rb + V_B);
#pragma unroll
                for (int hp = 0; hp < 2; hp++) {
                    int nt = p * 2 + hp;
                    MMA_BF16(o[nt], ph[t], bh[2 * hp], bh[2 * hp + 1]);
                    MMA_BF16(o[nt], ph[t], bl[2 * hp], bl[2 * hp + 1]);
                    MMA_BF16(o[nt], pl[t], bh[2 * hp], bh[2 * hp + 1]);
                }
            }
        }

        // cross-half reduction + epilogue
        if (wk == 1) {
#pragma unroll
            for (int nt = 0; nt < 4; nt++)
#pragma unroll
                for (int h = 0; h < 2; h++) {
                    int r = wm * 16 + gid + h * 8, cc = nt * 8 + tig * 2;
                    float2 v = {o[nt][h * 2 + 0], o[nt][h * 2 + 1]};
                    *(float2*)&ob[r * 34 + cc] = v;
                }
        }
        __syncthreads();
        if (wk == 0) {
#pragma unroll
            for (int nt = 0; nt < 4; nt++)
#pragma unroll
                for (int h = 0; h < 2; h++) {
                    int r = wm * 16 + gid + h * 8, cc = nt * 8 + tig * 2;
                    float2 part = *(float2*)&ob[r * 34 + cc];
                    int gr = q0 + r, gc = d * DCW + cc;
                    const float2 rv = *(const float2*)&repr[(rowbase + gr) * HID + gc];
                    float2 ov;
                    ov.x = rv.x + fmaxf(o[nt][h * 2 + 0] + part.x, 0.f);
                    ov.y = rv.y + fmaxf(o[nt][h * 2 + 1] + part.y, 0.f);
                    *(float2*)&out[(rowbase + gr) * HID + gc] = ov;
                }
        }
        __syncthreads();
    }
}

// ---------------------------------------------------------------------------
extern "C" void kernel_launch(void* const* d_in, const int* in_sizes, int n_in,
                              void* d_out, int out_size)
{
    (void)in_sizes; (void)n_in; (void)out_size;
    const float* repr = (const float*)d_in[0];
    const float* W    = (const float*)d_in[1];
    float* out        = (float*)d_out;

    repr_split_kernel<<<(M_TOT * HID) / (256 * 4), 256>>>(repr);
    dim3 tb(32, 8), tg(HID / 32, HID / 32);
    wt_split_kernel<<<tg, tb>>>(W);

    cudaFuncSetAttribute(gemm_bf16x3_kernel,
                         cudaFuncAttributeMaxDynamicSharedMemorySize, GEMM_SMEM);
    dim3 gg(HID / 128, M_TOT / 128);
    gemm_bf16x3_kernel<<<gg, 256, GEMM_SMEM>>>();

    cudaFuncSetAttribute(attn_tc_kernel,
                         cudaFuncAttributeMaxDynamicSharedMemorySize, ATTN_SMEM);
    dim3 ga(SEQ / 64, BATCH);
    attn_tc_kernel<<<ga, 256, ATTN_SMEM>>>(repr, out);
}

// round 6
// speedup vs baseline: 2.6840x; 1.0571x over previous
#include <cuda_runtime.h>
#include <cuda_bf16.h>
#include <cstdint>

#define BATCH 8
#define SEQ   2048
#define HID   1024
#define M_TOT (BATCH * SEQ)        // 16384
#define WHALF 64
#define NEG_INF -1e9f

// Scratch (__device__ globals; no allocation allowed)
__device__ __align__(16) __nv_bfloat16 g_qw_hi[(size_t)M_TOT * HID];
__device__ __align__(16) __nv_bfloat16 g_qw_lo[(size_t)M_TOT * HID];
__device__ __align__(16) __nv_bfloat16 g_a_hi[(size_t)M_TOT * HID];
__device__ __align__(16) __nv_bfloat16 g_a_lo[(size_t)M_TOT * HID];
__device__ __align__(16) __nv_bfloat16 g_wt_hi[(size_t)HID * HID];
__device__ __align__(16) __nv_bfloat16 g_wt_lo[(size_t)HID * HID];

// ---------------------------------------------------------------------------
// PTX helpers (architecture-neutral, sm_80-level)
// ---------------------------------------------------------------------------
__device__ __forceinline__ uint32_t smem_u32(const void* p) {
    uint32_t a;
    asm("{ .reg .u64 t; cvta.to.shared.u64 t, %1; cvt.u32.u64 %0, t; }" : "=r"(a) : "l"(p));
    return a;
}

#define CP_ASYNC16(dst_u32, src_ptr) \
    asm volatile("cp.async.cg.shared.global [%0], [%1], 16;" :: "r"(dst_u32), "l"(src_ptr))
#define CP_COMMIT() asm volatile("cp.async.commit_group;" ::: "memory")
#define CP_WAIT(n)  asm volatile("cp.async.wait_group %0;" :: "n"(n) : "memory")

#define LDMATRIX_X4(r0, r1, r2, r3, addr) \
    asm volatile("ldmatrix.sync.aligned.m8n8.x4.shared.b16 {%0,%1,%2,%3}, [%4];" \
                 : "=r"(r0), "=r"(r1), "=r"(r2), "=r"(r3) : "r"(addr))
#define LDMATRIX_X4_TRANS(r0, r1, r2, r3, addr) \
    asm volatile("ldmatrix.sync.aligned.m8n8.x4.trans.shared.b16 {%0,%1,%2,%3}, [%4];" \
                 : "=r"(r0), "=r"(r1), "=r"(r2), "=r"(r3) : "r"(addr))

#define MMA_BF16(d, a, b0v, b1v) \
    asm volatile("mma.sync.aligned.m16n8k16.row.col.f32.bf16.bf16.f32 " \
                 "{%0,%1,%2,%3},{%4,%5,%6,%7},{%8,%9},{%0,%1,%2,%3};" \
                 : "+f"((d)[0]), "+f"((d)[1]), "+f"((d)[2]), "+f"((d)[3]) \
                 : "r"((a)[0]), "r"((a)[1]), "r"((a)[2]), "r"((a)[3]), \
                   "r"(b0v), "r"(b1v))

__device__ __forceinline__ void split_pack(float a, float b, uint32_t& hi, uint32_t& lo) {
    __nv_bfloat16 ha = __float2bfloat16_rn(a);
    __nv_bfloat16 hb = __float2bfloat16_rn(b);
    __nv_bfloat16 la = __float2bfloat16_rn(a - __bfloat162float(ha));
    __nv_bfloat16 lb = __float2bfloat16_rn(b - __bfloat162float(hb));
    __nv_bfloat16 hp[2] = {ha, hb};
    __nv_bfloat16 lp[2] = {la, lb};
    hi = *(uint32_t*)hp;
    lo = *(uint32_t*)lp;
}

// ---------------------------------------------------------------------------
// Prep 1: repr -> a_hi/a_lo (bf16)
// ---------------------------------------------------------------------------
__global__ __launch_bounds__(256) void repr_split_kernel(const float* __restrict__ r) {
    size_t i = ((size_t)blockIdx.x * 256 + threadIdx.x) * 4;
    float4 v = *(const float4*)&r[i];
    uint32_t h0, l0, h1, l1;
    split_pack(v.x, v.y, h0, l0);
    split_pack(v.z, v.w, h1, l1);
    uint2 hh = {h0, h1}, ll = {l0, l1};
    *(uint2*)&g_a_hi[i] = hh;
    *(uint2*)&g_a_lo[i] = ll;
}

// ---------------------------------------------------------------------------
// Prep 2: W[k][n] -> Wt_hi/Wt_lo [n][k]
// ---------------------------------------------------------------------------
__global__ void wt_split_kernel(const float* __restrict__ W) {
    __shared__ float t[32][33];
    int bx = blockIdx.x * 32, by = blockIdx.y * 32;
    int x = threadIdx.x, y0 = threadIdx.y;
#pragma unroll
    for (int i = 0; i < 32; i += 8)
        t[y0 + i][x] = W[(size_t)(by + y0 + i) * HID + bx + x];
    __syncthreads();
#pragma unroll
    for (int i = 0; i < 32; i += 8) {
        float v = t[x][y0 + i];
        size_t o = (size_t)(bx + y0 + i) * HID + by + x;
        __nv_bfloat16 hi = __float2bfloat16_rn(v);
        g_wt_hi[o] = hi;
        g_wt_lo[o] = __float2bfloat16_rn(v - __bfloat162float(hi));
    }
}

// ---------------------------------------------------------------------------
// Kernel 1: bf16x3 GEMM  QW = repr @ W, bf16 hi/lo output
// ---------------------------------------------------------------------------
#define KB   32
#define NCH  (HID / KB)
#define TPCH 40
#define TILE_B  (128 * TPCH * 2)
#define STAGE_B (4 * TILE_B)
#define GEMM_SMEM (2 * STAGE_B)

__global__ __launch_bounds__(256, 2) void gemm_bf16x3_kernel() {
    extern __shared__ char sm[];
    const uint32_t smBase = smem_u32(sm);

    const int tid  = threadIdx.x;
    const int w    = tid >> 5;
    const int lane = tid & 31;
    const int wm   = w & 1;
    const int wn   = w >> 1;
    const int m0   = blockIdx.y * 128;
    const int n0   = blockIdx.x * 128;

    float acc[4][4][4];
#pragma unroll
    for (int i = 0; i < 4; i++)
#pragma unroll
        for (int j = 0; j < 4; j++)
#pragma unroll
            for (int q = 0; q < 4; q++) acc[i][j][q] = 0.f;

    auto load_chunk = [&](int stage, int c) {
        const int k0 = c * KB;
        const uint32_t sb = smBase + stage * STAGE_B;
#pragma unroll
        for (int i = 0; i < 2; i++) {
            int ch  = tid + i * 256;
            int row = ch >> 2, seg = ch & 3;
            uint32_t doff = (uint32_t)(row * (TPCH * 2) + seg * 16);
            size_t ga = (size_t)(m0 + row) * HID + k0 + seg * 8;
            size_t gb = (size_t)(n0 + row) * HID + k0 + seg * 8;
            CP_ASYNC16(sb + doff,              &g_a_hi[ga]);
            CP_ASYNC16(sb + TILE_B + doff,     &g_a_lo[ga]);
            CP_ASYNC16(sb + 2 * TILE_B + doff, &g_wt_hi[gb]);
            CP_ASYNC16(sb + 3 * TILE_B + doff, &g_wt_lo[gb]);
        }
    };

    load_chunk(0, 0);
    CP_COMMIT();

    for (int c = 0; c < NCH; c++) {
        if (c + 1 < NCH) {
            load_chunk((c + 1) & 1, c + 1);
            CP_COMMIT();
            CP_WAIT(1);
        } else {
            CP_WAIT(0);
        }
        __syncthreads();

        const uint32_t sb = smBase + (c & 1) * STAGE_B;
#pragma unroll
        for (int ks = 0; ks < KB; ks += 16) {
            uint32_t ah[4][4], al[4][4], bh[2][4], bl[2][4];
            const uint32_t cofs = (uint32_t)((ks + ((lane >> 4) << 3)) * 2);
#pragma unroll
            for (int mt = 0; mt < 4; mt++) {
                uint32_t ra = sb + (uint32_t)((wm * 64 + mt * 16 + (lane & 15)) * (TPCH * 2)) + cofs;
                LDMATRIX_X4(ah[mt][0], ah[mt][1], ah[mt][2], ah[mt][3], ra);
                LDMATRIX_X4(al[mt][0], al[mt][1], al[mt][2], al[mt][3], ra + TILE_B);
            }
#pragma unroll
            for (int np = 0; np < 2; np++) {
                uint32_t rb = sb + 2 * TILE_B +
                              (uint32_t)((wn * 32 + np * 16 + (lane & 15)) * (TPCH * 2)) + cofs;
                LDMATRIX_X4(bh[np][0], bh[np][1], bh[np][2], bh[np][3], rb);
                LDMATRIX_X4(bl[np][0], bl[np][1], bl[np][2], bl[np][3], rb + TILE_B);
            }
#pragma unroll
            for (int mt = 0; mt < 4; mt++)
#pragma unroll
                for (int nt = 0; nt < 4; nt++) {
                    const int np = nt >> 1, hp = nt & 1;
                    MMA_BF16(acc[mt][nt], ah[mt], bh[np][hp], bh[np][hp + 2]);
                    MMA_BF16(acc[mt][nt], ah[mt], bl[np][hp], bl[np][hp + 2]);
                    MMA_BF16(acc[mt][nt], al[mt], bh[np][hp], bh[np][hp + 2]);
                }
        }
        __syncthreads();
    }

    const int gid = lane >> 2, tig = lane & 3;
#pragma unroll
    for (int mt = 0; mt < 4; mt++) {
#pragma unroll
        for (int nt = 0; nt < 4; nt++) {
#pragma unroll
            for (int h = 0; h < 2; h++) {
                int r  = m0 + wm * 64 + mt * 16 + gid + h * 8;
                int cc = n0 + wn * 32 + nt * 8 + tig * 2;
                uint32_t hp2, lp2;
                split_pack(acc[mt][nt][h * 2 + 0], acc[mt][nt][h * 2 + 1], hp2, lp2);
                *(uint32_t*)&g_qw_hi[(size_t)r * HID + cc] = hp2;
                *(uint32_t*)&g_qw_lo[(size_t)r * HID + cc] = lp2;
            }
        }
    }
}

// ---------------------------------------------------------------------------
// Kernel 2: tensor-core windowed attention, register-resident P
// Phase 1: S frags in regs (bf16x3 over K=1024, cp.async double-buffered).
// Phase 2: softmax on frags -> P hi/lo frags in regs.
// Phase 3: dc-chunks of 64 cols; V bf16-hi only, double-buffered; 2-term
// P·V (ph·vh + pl·vh); cross-half smem reduction; residual+relu epilogue.
// ---------------------------------------------------------------------------
#define APITCH 40                    // bf16 pitch (80 B rows)
#define AQ_B   (64 * APITCH * 2)     // 5120
#define AK_B   (192 * APITCH * 2)    // 15360
#define A_STG  (2 * AQ_B + 2 * AK_B) // 40960: Qh | Ql | Kh | Kl
#define DCW 64
#define NDC (HID / DCW)              // 16
#define VPITCH 72                    // bf16 pitch for 64-col V rows (144 B)
#define V_B    (192 * VPITCH * 2)    // 27648 per stage (hi only)
#define OBUF_OFF 55296               // 64 x 68 fp32 = 17408
#define OPITCH 68
#define STAT_OFF 81920               // max[128] + sum[128] fp32 = 1024
#define ATTN_SMEM (STAT_OFF + 1024)  // 82944

__global__ __launch_bounds__(256, 2) void attn_tc_kernel(
    const float* __restrict__ repr, float* __restrict__ out)
{
    extern __shared__ char sm[];
    const uint32_t smb = smem_u32(sm);

    const int tid  = threadIdx.x;
    const int w    = tid >> 5;
    const int lane = tid & 31;
    const int gid  = lane >> 2, tig = lane & 3;
    const int wm   = w & 3;
    const int wk   = w >> 2;

    const int b  = blockIdx.y;
    const int q0 = blockIdx.x * 64;
    const int k0 = q0 - WHALF;
    const size_t rowbase = (size_t)b * SEQ;

    // ---------------- Phase 1: S = Q·K^T (frags in regs) -----------------
    auto load_qk = [&](int stage, int c) {
        const int kd = c * KB;
        const uint32_t sb = smb + stage * A_STG;
        {
            int row = tid >> 2, seg = tid & 3;
            uint32_t off = (uint32_t)(row * (APITCH * 2) + seg * 16);
            size_t ga = (rowbase + q0 + row) * HID + kd + seg * 8;
            CP_ASYNC16(sb + off,        &g_qw_hi[ga]);
            CP_ASYNC16(sb + AQ_B + off, &g_qw_lo[ga]);
        }
#pragma unroll
        for (int rep = 0; rep < 3; rep++) {
            int idx = tid + rep * 256;
            int row = idx >> 2, seg = idx & 3;
            int j = k0 + row;
            j = j < 0 ? 0 : (j >= SEQ ? SEQ - 1 : j);   // clamp; masked later
            uint32_t off = (uint32_t)(row * (APITCH * 2) + seg * 16);
            size_t ga = (rowbase + j) * HID + kd + seg * 8;
            CP_ASYNC16(sb + 2 * AQ_B + off,        &g_a_hi[ga]);
            CP_ASYNC16(sb + 2 * AQ_B + AK_B + off, &g_a_lo[ga]);
        }
    };

    float acc[12][4];
#pragma unroll
    for (int i = 0; i < 12; i++)
#pragma unroll
        for (int q = 0; q < 4; q++) acc[i][q] = 0.f;

    load_qk(0, 0);
    CP_COMMIT();

    for (int c = 0; c < NCH; c++) {
        if (c + 1 < NCH) { load_qk((c + 1) & 1, c + 1); CP_COMMIT(); CP_WAIT(1); }
        else             { CP_WAIT(0); }
        __syncthreads();
        const uint32_t sb = smb + (c & 1) * A_STG;
#pragma unroll
        for (int ks = 0; ks < 2; ks++) {
            const uint32_t cofs = (uint32_t)((ks * 16 + ((lane >> 4) << 3)) * 2);
            uint32_t ah[4], al[4];
            uint32_t ra = sb + (uint32_t)((wm * 16 + (lane & 15)) * (APITCH * 2)) + cofs;
            LDMATRIX_X4(ah[0], ah[1], ah[2], ah[3], ra);
            LDMATRIX_X4(al[0], al[1], al[2], al[3], ra + AQ_B);
#pragma unroll
            for (int p = 0; p < 6; p++) {
                uint32_t bh[4], bl[4];
                uint32_t rb = sb + 2 * AQ_B +
                    (uint32_t)((wk * 96 + p * 16 + (lane & 15)) * (APITCH * 2)) + cofs;
                LDMATRIX_X4(bh[0], bh[1], bh[2], bh[3], rb);
                LDMATRIX_X4(bl[0], bl[1], bl[2], bl[3], rb + AK_B);
#pragma unroll
                for (int hp = 0; hp < 2; hp++) {
                    int nt = p * 2 + hp;
                    MMA_BF16(acc[nt], ah, bh[hp], bh[hp + 2]);
                    MMA_BF16(acc[nt], ah, bl[hp], bl[hp + 2]);
                    MMA_BF16(acc[nt], al, bh[hp], bh[hp + 2]);
                }
            }
        }
        __syncthreads();
    }

    // ---------------- Phase 2: softmax on register fragments -------------
#pragma unroll
    for (int nt = 0; nt < 12; nt++) {
#pragma unroll
        for (int h = 0; h < 2; h++) {
            int row = wm * 16 + gid + h * 8;
#pragma unroll
            for (int e = 0; e < 2; e++) {
                int col = wk * 96 + nt * 8 + tig * 2 + e;
                int j = k0 + col, dr = col - row;
                if (!((j >= 0) && (j < SEQ) && (dr >= 0) && (dr <= 2 * WHALF)))
                    acc[nt][h * 2 + e] = NEG_INF;
            }
        }
    }

    float* statb = (float*)(sm + STAT_OFF);
    float mrow[2] = {NEG_INF, NEG_INF};
#pragma unroll
    for (int nt = 0; nt < 12; nt++) {
        mrow[0] = fmaxf(mrow[0], fmaxf(acc[nt][0], acc[nt][1]));
        mrow[1] = fmaxf(mrow[1], fmaxf(acc[nt][2], acc[nt][3]));
    }
#pragma unroll
    for (int h = 0; h < 2; h++) {
        mrow[h] = fmaxf(mrow[h], __shfl_xor_sync(0xffffffffu, mrow[h], 1));
        mrow[h] = fmaxf(mrow[h], __shfl_xor_sync(0xffffffffu, mrow[h], 2));
    }
    if (tig == 0) {
        statb[wk * 64 + wm * 16 + gid]     = mrow[0];
        statb[wk * 64 + wm * 16 + gid + 8] = mrow[1];
    }
    __syncthreads();
    mrow[0] = fmaxf(mrow[0], statb[(1 - wk) * 64 + wm * 16 + gid]);
    mrow[1] = fmaxf(mrow[1], statb[(1 - wk) * 64 + wm * 16 + gid + 8]);

    float srow[2] = {0.f, 0.f};
#pragma unroll
    for (int nt = 0; nt < 12; nt++) {
#pragma unroll
        for (int h = 0; h < 2; h++) {
#pragma unroll
            for (int e = 0; e < 2; e++) {
                float ex = __expf(acc[nt][h * 2 + e] - mrow[h]);
                acc[nt][h * 2 + e] = ex;
                srow[h] += ex;
            }
        }
    }
#pragma unroll
    for (int h = 0; h < 2; h++) {
        srow[h] += __shfl_xor_sync(0xffffffffu, srow[h], 1);
        srow[h] += __shfl_xor_sync(0xffffffffu, srow[h], 2);
    }
    float* sumb = statb + 128;
    if (tig == 0) {
        sumb[wk * 64 + wm * 16 + gid]     = srow[0];
        sumb[wk * 64 + wm * 16 + gid + 8] = srow[1];
    }
    __syncthreads();
    float inv0 = 1.f / (srow[0] + sumb[(1 - wk) * 64 + wm * 16 + gid]);
    float inv1 = 1.f / (srow[1] + sumb[(1 - wk) * 64 + wm * 16 + gid + 8]);

    uint32_t ph[6][4], pl[6][4];
#pragma unroll
    for (int t = 0; t < 6; t++) {
        split_pack(acc[2 * t][0] * inv0,     acc[2 * t][1] * inv0,     ph[t][0], pl[t][0]);
        split_pack(acc[2 * t][2] * inv1,     acc[2 * t][3] * inv1,     ph[t][1], pl[t][1]);
        split_pack(acc[2 * t + 1][0] * inv0, acc[2 * t + 1][1] * inv0, ph[t][2], pl[t][2]);
        split_pack(acc[2 * t + 1][2] * inv1, acc[2 * t + 1][3] * inv1, ph[t][3], pl[t][3]);
    }
    __syncthreads();

    // ---------------- Phase 3: O = P·V, dc=64, V hi-only, 2-term ---------
    auto load_v = [&](int stage, int d) {
        const int d0 = d * DCW;
        const uint32_t sb = smb + stage * V_B;
#pragma unroll
        for (int rep = 0; rep < 6; rep++) {
            int idx = tid + rep * 256;
            int vr = idx >> 3, seg = idx & 7;
            int j = k0 + vr;
            j = j < 0 ? 0 : (j >= SEQ ? SEQ - 1 : j);   // clamp; P=0 there
            uint32_t off = (uint32_t)(vr * (VPITCH * 2) + seg * 16);
            CP_ASYNC16(sb + off, &g_a_hi[(rowbase + j) * HID + d0 + seg * 8]);
        }
    };

    load_v(0, 0);
    CP_COMMIT();

    float* ob = (float*)(sm + OBUF_OFF);

    for (int d = 0; d < NDC; d++) {
        if (d + 1 < NDC) { load_v((d + 1) & 1, d + 1); CP_COMMIT(); CP_WAIT(1); }
        else             { CP_WAIT(0); }
        __syncthreads();
        const uint32_t vb = smb + (d & 1) * V_B;

        float o[8][4];
#pragma unroll
        for (int i = 0; i < 8; i++)
#pragma unroll
            for (int q = 0; q < 4; q++) o[i][q] = 0.f;

#pragma unroll
        for (int t = 0; t < 6; t++) {
            const int krow = wk * 96 + t * 16;
#pragma unroll
            for (int p = 0; p < 4; p++) {
                uint32_t vh[4];
                uint32_t rb = vb + (uint32_t)((krow + (lane & 15)) * (VPITCH * 2)) +
                              (uint32_t)((p * 16 + ((lane >> 4) << 3)) * 2);
                LDMATRIX_X4_TRANS(vh[0], vh[1], vh[2], vh[3], rb);
#pragma unroll
                for (int hp = 0; hp < 2; hp++) {
                    int nt = p * 2 + hp;
                    MMA_BF16(o[nt], ph[t], vh[2 * hp], vh[2 * hp + 1]);
                    MMA_BF16(o[nt], pl[t], vh[2 * hp], vh[2 * hp + 1]);
                }
            }
        }

        if (wk == 1) {
#pragma unroll
            for (int nt = 0; nt < 8; nt++)
#pragma unroll
                for (int h = 0; h < 2; h++) {
                    int r = wm * 16 + gid + h * 8, cc = nt * 8 + tig * 2;
                    float2 v = {o[nt][h * 2 + 0], o[nt][h * 2 + 1]};
                    *(float2*)&ob[r * OPITCH + cc] = v;
                }
        }
        __syncthreads();
        if (wk == 0) {
#pragma unroll
            for (int nt = 0; nt < 8; nt++)
#pragma unroll
                for (int h = 0; h < 2; h++) {
                    int r = wm * 16 + gid + h * 8, cc = nt * 8 + tig * 2;
                    float2 part = *(float2*)&ob[r * OPITCH + cc];
                    int gr = q0 + r, gc = d * DCW + cc;
                    const float2 rv = *(const float2*)&repr[(rowbase + gr) * HID + gc];
                    float2 ov;
                    ov.x = rv.x + fmaxf(o[nt][h * 2 + 0] + part.x, 0.f);
                    ov.y = rv.y + fmaxf(o[nt][h * 2 + 1] + part.y, 0.f);
                    *(float2*)&out[(rowbase + gr) * HID + gc] = ov;
                }
        }
        __syncthreads();
    }
}

// ---------------------------------------------------------------------------
extern "C" void kernel_launch(void* const* d_in, const int* in_sizes, int n_in,
                              void* d_out, int out_size)
{
    (void)in_sizes; (void)n_in; (void)out_size;
    const float* repr = (const float*)d_in[0];
    const float* W    = (const float*)d_in[1];
    float* out        = (float*)d_out;

    repr_split_kernel<<<(M_TOT * HID) / (256 * 4), 256>>>(repr);
    dim3 tb(32, 8), tg(HID / 32, HID / 32);
    wt_split_kernel<<<tg, tb>>>(W);

    cudaFuncSetAttribute(gemm_bf16x3_kernel,
                         cudaFuncAttributeMaxDynamicSharedMemorySize, GEMM_SMEM);
    dim3 gg(HID / 128, M_TOT / 128);
    gemm_bf16x3_kernel<<<gg, 256, GEMM_SMEM>>>();

    cudaFuncSetAttribute(attn_tc_kernel,
                         cudaFuncAttributeMaxDynamicSharedMemorySize, ATTN_SMEM);
    dim3 ga(SEQ / 64, BATCH);
    attn_tc_kernel<<<ga, 256, ATTN_SMEM>>>(repr, out);
}